// round 15
// baseline (speedup 1.0000x reference)
#include <cuda_runtime.h>
#include <cuda_bf16.h>
#include <cstdint>

#define NUM_USER     200000
#define NUM_QUESTION 20000
#define NC           128
#define DH           512
#define H2           256
#define BATCH        16384
#define MAXE         384
#define KW           (NC / 2)
#define DHW          (DH / 2)

// k_factor: single stage, BK=128 (whole K). 384 rows x 68 u32.
#define LDSF         68
#define SMEM_FACTOR  (384 * LDSF * 4)     // 104448 B
// k_mlp: BK=64, stage = 256 rows x 36 u32, 3 stages
#define LDS2         36
#define M_STAGEU     (256 * LDS2)
#define SMEM_MLP     (3 * M_STAGEU * 4)   // 110592 B

#define NB_MAST      (BATCH / 8)
#define NB_PACK      ((BATCH * KW + 255) / 256)

// ---------------- scratch (__device__ globals) ----------------
__device__ uint32_t g_Bm2[BATCH * KW];
__device__ float    g_Disc[BATCH];
__device__ uint32_t g_A2 [BATCH * KW];
__device__ uint32_t g_X2 [BATCH * DHW];
__device__ float    g_P  [2 * BATCH];
__device__ int      g_cnt[BATCH / 128];
__device__ uint32_t g_Wu2[DH * KW];
__device__ uint32_t g_Wi2[DH * KW];
__device__ uint32_t g_W12[H2 * DHW];

struct Sched {
    unsigned char  order[NC];
    unsigned char  lp[NC];
    unsigned short off[NC];
    unsigned char  pred[NC][3];
    float          invl[NC];
    short          lvlStart[NC + 1];
    int            nLvl;
};

__device__ __forceinline__ float sigmoidf(float x) {          // exact (final combine)
    return __fdividef(1.0f, 1.0f + __expf(-x));
}
__device__ __forceinline__ float tanha(float x) {             // 1 MUFU
    float y;
    asm("tanh.approx.f32 %0, %1;" : "=f"(y) : "f"(x));
    return y;
}
__device__ __forceinline__ float sigma(float x) {             // 1 MUFU + FMA
    return fmaf(tanha(0.5f * x), 0.5f, 0.5f);
}
__device__ __forceinline__ float sqrta(float x) {             // 1 MUFU
    float y;
    asm("sqrt.approx.f32 %0, %1;" : "=f"(y) : "f"(x));
    return y;
}
__device__ __forceinline__ uint32_t packbf(float x, float y) {
    __nv_bfloat162 v = __floats2bfloat162_rn(x, y);
    return *(uint32_t*)&v;
}
__device__ __forceinline__ uint32_t smem_u32(const void* p) {
    uint32_t a;
    asm("{ .reg .u64 t; cvta.to.shared.u64 t, %1; cvt.u32.u64 %0, t; }" : "=r"(a) : "l"(p));
    return a;
}
__device__ __forceinline__ void cp16(uint32_t s, const void* g) {
    asm volatile("cp.async.cg.shared.global [%0], [%1], 16;" :: "r"(s), "l"(g));
}
__device__ __forceinline__ void cp_commit() {
    asm volatile("cp.async.commit_group;" ::: "memory");
}
__device__ __forceinline__ void cp_wait0() {
    asm volatile("cp.async.wait_group 0;" ::: "memory");
}
__device__ __forceinline__ void cp_wait1() {
    asm volatile("cp.async.wait_group 1;" ::: "memory");
}
__device__ __forceinline__ void ldsm4(uint32_t r[4], uint32_t addr) {
    asm volatile("ldmatrix.sync.aligned.m8n8.x4.shared.b16 {%0,%1,%2,%3}, [%4];"
        : "=r"(r[0]), "=r"(r[1]), "=r"(r[2]), "=r"(r[3]) : "r"(addr));
}
__device__ __forceinline__ void mma_bf16(float c[4],
                                         uint32_t a0, uint32_t a1, uint32_t a2, uint32_t a3,
                                         uint32_t b0, uint32_t b1) {
    asm volatile(
        "mma.sync.aligned.m16n8k16.row.col.f32.bf16.bf16.f32 "
        "{%0,%1,%2,%3}, {%4,%5,%6,%7}, {%8,%9}, {%0,%1,%2,%3};"
        : "+f"(c[0]), "+f"(c[1]), "+f"(c[2]), "+f"(c[3])
        : "r"(a0), "r"(a1), "r"(a2), "r"(a3), "r"(b0), "r"(b1));
}

// ---------------- K0: merged front end -------------------------------------
#define WPB 8
#define NIT (MAXE / 32)
__global__ void __launch_bounds__(256) k_front(
    const int* __restrict__ uid, const int* __restrict__ qid,
    const float* __restrict__ priori,
    const float* __restrict__ condi_p, const float* __restrict__ condi_n,
    const float* __restrict__ qt,
    const float* __restrict__ idiff, const float* __restrict__ idisc,
    const float* __restrict__ Wu, const float* __restrict__ Wi,
    const float* __restrict__ W1,
    Sched s, int E)
{
    if (blockIdx.x >= NB_MAST) {
        // ---- pack part ----
        int idx = (blockIdx.x - NB_MAST) * blockDim.x + threadIdx.x;
        if (idx >= BATCH * KW) return;
        if (idx < DH * KW) {
            g_Wu2[idx] = packbf(Wu[2 * idx], Wu[2 * idx + 1]);
            g_Wi2[idx] = packbf(Wi[2 * idx], Wi[2 * idx + 1]);
        }
        if (idx < H2 * DHW)
            g_W12[idx] = packbf(W1[2 * idx], W1[2 * idx + 1]);
        int b = idx >> 6, j = idx & 63;
        int q = qid[b];
        size_t base = (size_t)q * NC + 2 * j;
        float v0 = sigma(idiff[base])     * qt[base];
        float v1 = sigma(idiff[base + 1]) * qt[base + 1];
        g_Bm2[idx] = packbf(v0, v1);
        if (j == 0) g_Disc[b] = sigma(idisc[q]);
        return;
    }

    // ---- mastery part ----
    __shared__ float sm_m [WPB][NC];
    __shared__ float sm_cp[WPB][MAXE];
    __shared__ float sm_cn[WPB][MAXE];

    int lane = threadIdx.x & 31, w = threadIdx.x >> 5;
    int b = blockIdx.x * WPB + w;
    int u = uid[b];

    const float* cpr = condi_p + (size_t)u * E;
    const float* cnr = condi_n + (size_t)u * E;

    float rcp[NIT], rcn[NIT];
    #pragma unroll
    for (int it = 0; it < NIT; it++) {
        int j = lane + it * 32;
        if (j < E) { rcp[it] = __ldg(cpr + j); rcn[it] = __ldg(cnr + j); }
    }
    #pragma unroll
    for (int it = 0; it < NIT; it++) {
        int j = lane + it * 32;
        if (j < E) {
            sm_cp[w][j] = sigma(rcp[it]);     // 1-MUFU sigmoid
            sm_cn[w][j] = sigma(rcn[it]);
        }
    }
    __syncwarp();

    const float* pr = priori + (size_t)u * NC;
    for (int lv = 0; lv < s.nLvl; lv++) {
        int e = s.lvlStart[lv + 1];
        for (int i = s.lvlStart[lv] + lane; i < e; i += 32) {
            int k = s.order[i];
            int l = s.lp[k];
            float v;
            if (l == 0) {
                v = sigma(pr[k]);
            } else {
                int o = s.off[k];
                float inv = s.invl[k];
                v = 1.0f;
                #pragma unroll 1
                for (int j = 0; j < l; j++) {
                    float mp = sm_m[w][s.pred[k][j]];
                    float a = sm_cp[w][o + j], bb = sm_cn[w][o + j];
                    if (l == 2)      { a = sqrta(a); bb = sqrta(bb); }
                    else if (l == 3) { a = __powf(a, inv); bb = __powf(bb, inv); }
                    v *= a * mp + bb * (1.0f - mp);
                }
            }
            sm_m[w][k] = v;
        }
        __syncwarp();
    }

    int q = qid[b];
    const float* qr = qt + (size_t)q * NC;
    uint32_t* ao = g_A2 + (size_t)b * KW;
    for (int j = lane; j < KW; j += 32)
        ao[j] = packbf(sm_m[w][2 * j] * qr[2 * j], sm_m[w][2 * j + 1] * qr[2 * j + 1]);
}

// ---------------- K2: fused dual bf16 GEMM -> X  (128M x 64N, BK=128, 1 stage) -----
__global__ void __launch_bounds__(256, 2) k_factor(const float* __restrict__ bu,
                                                   const float* __restrict__ bi)
{
    extern __shared__ uint32_t smx[];
    int t = threadIdx.x, lane = t & 31, warp = t >> 5;
    int wm = (warp & 1) * 64;
    int wn = (warp >> 1) * 16;
    int m0 = blockIdx.x * 128, n0 = blockIdx.y * 64;
    int g   = lane >> 2;
    int tig = lane & 3;
    int lr  = lane & 15;
    int lk  = (lane >> 4) * 4;

    const uint32_t* Ab  = g_A2  + (size_t)m0 * KW;
    const uint32_t* Bmb = g_Bm2 + (size_t)m0 * KW;
    const uint32_t* Wub = g_Wu2 + (size_t)n0 * KW;
    const uint32_t* Wib = g_Wi2 + (size_t)n0 * KW;

    int cr = t >> 4;
    int cc = (t & 15) * 4;

    uint32_t sb = smem_u32(smx);
    #pragma unroll
    for (int i = 0; i < 24; i++) {
        int smrow = i * 16 + cr;
        const uint32_t* src;
        if      (i < 8)  src = Ab  + (size_t)(i * 16 + cr) * KW;
        else if (i < 16) src = Bmb + (size_t)((i - 8) * 16 + cr) * KW;
        else if (i < 20) src = Wub + (size_t)((i - 16) * 16 + cr) * KW;
        else             src = Wib + (size_t)((i - 20) * 16 + cr) * KW;
        cp16(sb + (uint32_t)(smrow * LDSF + cc) * 4, src + cc);
    }
    cp_commit();
    cp_wait0();
    __syncthreads();

    float cU[4][2][4], cI[4][2][4];
    #pragma unroll
    for (int mi = 0; mi < 4; mi++)
        #pragma unroll
        for (int ni = 0; ni < 2; ni++)
            #pragma unroll
            for (int q = 0; q < 4; q++) { cU[mi][ni][q] = 0.f; cI[mi][ni][q] = 0.f; }

    #pragma unroll
    for (int kk = 0; kk < 8; kk++) {
        int kb = kk * 8;
        uint32_t fu[4], fi[4], aA[4][4], aB[4][4];
        ldsm4(fu, sb + 4u * ((256 + wn + lr) * LDSF + kb + lk));
        ldsm4(fi, sb + 4u * ((320 + wn + lr) * LDSF + kb + lk));
        #pragma unroll
        for (int mi = 0; mi < 4; mi++) {
            int rb = wm + mi * 16 + lr;
            ldsm4(aA[mi], sb + 4u * (rb * LDSF + kb + lk));
            ldsm4(aB[mi], sb + 4u * ((128 + rb) * LDSF + kb + lk));
        }
        #pragma unroll
        for (int mi = 0; mi < 4; mi++) {
            mma_bf16(cU[mi][0], aA[mi][0], aA[mi][1], aA[mi][2], aA[mi][3], fu[0], fu[2]);
            mma_bf16(cU[mi][1], aA[mi][0], aA[mi][1], aA[mi][2], aA[mi][3], fu[1], fu[3]);
            mma_bf16(cI[mi][0], aB[mi][0], aB[mi][1], aB[mi][2], aB[mi][3], fi[0], fi[2]);
            mma_bf16(cI[mi][1], aB[mi][0], aB[mi][1], aB[mi][2], aB[mi][3], fi[1], fi[3]);
        }
    }

    #pragma unroll
    for (int mi = 0; mi < 4; mi++) {
        int r0 = m0 + wm + mi * 16 + g;
        float d0 = g_Disc[r0], d1 = g_Disc[r0 + 8];
        #pragma unroll
        for (int ni = 0; ni < 2; ni++) {
            int col = n0 + wn + ni * 8 + tig * 2;
            float bu0 = bu[col], bu1 = bu[col + 1];
            float bi0 = bi[col], bi1 = bi[col + 1];
            float x00 = (tanha(cU[mi][ni][0] + bu0) - sigma(cI[mi][ni][0] + bi0)) * d0;
            float x01 = (tanha(cU[mi][ni][1] + bu1) - sigma(cI[mi][ni][1] + bi1)) * d0;
            float x10 = (tanha(cU[mi][ni][2] + bu0) - sigma(cI[mi][ni][2] + bi0)) * d1;
            float x11 = (tanha(cU[mi][ni][3] + bu1) - sigma(cI[mi][ni][3] + bi1)) * d1;
            g_X2[(size_t)r0 * DHW + (col >> 1)]       = packbf(x00, x01);
            g_X2[(size_t)(r0 + 8) * DHW + (col >> 1)] = packbf(x10, x11);
        }
    }
}

// ---------------- K3: bf16 GEMM + fused GEMV + final combine ----------------
__global__ void __launch_bounds__(256, 2) k_mlp(const float* __restrict__ bias,
                                                const float* __restrict__ W2,
                                                const float* __restrict__ b2,
                                                float* __restrict__ out)
{
    extern __shared__ uint32_t smx[];
    int t = threadIdx.x, lane = t & 31, warp = t >> 5;
    int wm = (warp & 1) * 64;
    int wn = (warp >> 1) * 32;
    int m0 = blockIdx.x * 128, n0 = blockIdx.y * 128;
    int g   = lane >> 2;
    int tig = lane & 3;
    int lr  = lane & 15;
    int lk  = (lane >> 4) * 4;

    const uint32_t* Ab = g_X2  + (size_t)m0 * DHW;
    const uint32_t* Wb = g_W12 + (size_t)n0 * DHW;

    int cr = t >> 3;
    int cc = (t & 7) * 4;

    float acc[4][4][4];
    #pragma unroll
    for (int mi = 0; mi < 4; mi++)
        #pragma unroll
        for (int ni = 0; ni < 4; ni++)
            #pragma unroll
            for (int q = 0; q < 4; q++) acc[mi][ni][q] = 0.f;

    const int NCH = 8;

    auto issue = [&](int ch, uint32_t* st) {
        uint32_t sb = smem_u32(st);
        int kc = ch * 32;
        #pragma unroll
        for (int i = 0; i < 8; i++) {
            int smrow = i * 32 + cr;
            const uint32_t* src = (i < 4) ? Ab + (size_t)(i * 32 + cr) * DHW
                                          : Wb + (size_t)((i - 4) * 32 + cr) * DHW;
            cp16(sb + (uint32_t)(smrow * LDS2 + cc) * 4, src + kc + cc);
        }
    };

    issue(0, smx);             cp_commit();
    issue(1, smx + M_STAGEU);  cp_commit();

    #pragma unroll
    for (int ch = 0; ch < NCH; ch++) {
        cp_wait1();
        __syncthreads();
        if (ch + 2 < NCH) {
            int s2 = (ch + 2) % 3;
            issue(ch + 2, smx + s2 * M_STAGEU);
        }
        cp_commit();
        uint32_t sb = smem_u32(smx + (ch % 3) * M_STAGEU);
        #pragma unroll
        for (int kk = 0; kk < 4; kk++) {
            int kb = kk * 8;
            uint32_t f0[4], f1[4], a[4][4];
            ldsm4(f0, sb + 4u * ((128 + wn + lr) * LDS2 + kb + lk));
            ldsm4(f1, sb + 4u * ((144 + wn + lr) * LDS2 + kb + lk));
            #pragma unroll
            for (int mi = 0; mi < 4; mi++)
                ldsm4(a[mi], sb + 4u * ((wm + mi * 16 + lr) * LDS2 + kb + lk));
            #pragma unroll
            for (int mi = 0; mi < 4; mi++) {
                mma_bf16(acc[mi][0], a[mi][0], a[mi][1], a[mi][2], a[mi][3], f0[0], f0[2]);
                mma_bf16(acc[mi][1], a[mi][0], a[mi][1], a[mi][2], a[mi][3], f0[1], f0[3]);
                mma_bf16(acc[mi][2], a[mi][0], a[mi][1], a[mi][2], a[mi][3], f1[0], f1[2]);
                mma_bf16(acc[mi][3], a[mi][0], a[mi][1], a[mi][2], a[mi][3], f1[1], f1[3]);
            }
        }
        __syncthreads();
    }

    float w2v[8], bv[8];
    #pragma unroll
    for (int ni = 0; ni < 4; ni++) {
        int col = n0 + wn + ni * 8 + tig * 2;
        w2v[ni * 2]     = W2[col];
        w2v[ni * 2 + 1] = W2[col + 1];
        bv [ni * 2]     = bias[col];
        bv [ni * 2 + 1] = bias[col + 1];
    }
    float part[8];
    #pragma unroll
    for (int j = 0; j < 8; j++) part[j] = 0.f;
    #pragma unroll
    for (int mi = 0; mi < 4; mi++)
        #pragma unroll
        for (int ni = 0; ni < 4; ni++) {
            float b0 = bv[ni * 2], b1v = bv[ni * 2 + 1];
            float w0 = w2v[ni * 2], w1 = w2v[ni * 2 + 1];
            part[mi * 2]     += sigma(acc[mi][ni][0] + b0) * w0
                              + sigma(acc[mi][ni][1] + b1v) * w1;
            part[mi * 2 + 1] += sigma(acc[mi][ni][2] + b0) * w0
                              + sigma(acc[mi][ni][3] + b1v) * w1;
        }
    #pragma unroll
    for (int j = 0; j < 8; j++) {
        part[j] += __shfl_xor_sync(0xffffffffu, part[j], 1);
        part[j] += __shfl_xor_sync(0xffffffffu, part[j], 2);
    }
    float* sP = (float*)smx;
    if (tig == 0) {
        #pragma unroll
        for (int mi = 0; mi < 4; mi++) {
            int rl = wm + mi * 16 + g;
            sP[(warp >> 1) * 128 + rl]     = part[mi * 2];
            sP[(warp >> 1) * 128 + rl + 8] = part[mi * 2 + 1];
        }
    }
    __syncthreads();
    if (t < 128) {
        float s = sP[t] + sP[128 + t] + sP[256 + t] + sP[384 + t];
        g_P[(size_t)blockIdx.y * BATCH + m0 + t] = s;
    }

    __threadfence();
    __syncthreads();
    __shared__ int s_old;
    if (t == 0) s_old = atomicAdd(&g_cnt[blockIdx.x], 1);
    __syncthreads();
    if (s_old == 1) {
        __threadfence();
        if (t < 128) {
            float s = g_P[m0 + t] + g_P[BATCH + m0 + t] + b2[0];
            out[m0 + t] = sigmoidf(s);
        }
        if (t == 0) g_cnt[blockIdx.x] = 0;
    }
}

// ---------------- host: numpy-legacy MT19937 graph reconstruction ----------------
namespace {
struct MT { uint32_t mt[624]; int idx; };
static void mt_seed(MT& s, uint32_t seed) {
    s.mt[0] = seed;
    for (int i = 1; i < 624; i++)
        s.mt[i] = 1812433253u * (s.mt[i-1] ^ (s.mt[i-1] >> 30)) + (uint32_t)i;
    s.idx = 624;
}
static uint32_t mt_next(MT& s) {
    if (s.idx >= 624) {
        for (int i = 0; i < 624; i++) {
            uint32_t y = (s.mt[i] & 0x80000000u) | (s.mt[(i+1) % 624] & 0x7fffffffu);
            s.mt[i] = s.mt[(i+397) % 624] ^ (y >> 1) ^ ((y & 1u) ? 0x9908b0dfu : 0u);
        }
        s.idx = 0;
    }
    uint32_t y = s.mt[s.idx++];
    y ^= y >> 11;
    y ^= (y << 7)  & 0x9d2c5680u;
    y ^= (y << 15) & 0xefc60000u;
    y ^= y >> 18;
    return y;
}
static uint32_t draw_bounded(MT& s, uint32_t rng) {
    uint32_t mask = rng; mask |= mask >> 1; mask |= mask >> 2; mask |= mask >> 4;
    mask |= mask >> 8; mask |= mask >> 16;
    uint32_t v;
    do { v = mt_next(s) & mask; } while (v > rng);
    return v;
}
static void build_graph(Sched& sc, int& E) {
    MT mt; mt_seed(mt, 0u);
    int off = 0;
    int level[NC];
    for (int k = 0; k < NC; k++) {
        int l = 0;
        if (k > 0) {
            int hi = (k < 3 ? k : 3) + 1;
            l = (int)draw_bounded(mt, (uint32_t)(hi - 1));
        }
        int preds[3] = {0, 0, 0};
        if (l > 0) {
            int arr[NC];
            for (int i = 0; i < k; i++) arr[i] = i;
            for (int i = k - 1; i >= 1; i--) {
                uint32_t j = draw_bounded(mt, (uint32_t)i);
                int tmp = arr[i]; arr[i] = arr[(int)j]; arr[(int)j] = tmp;
            }
            for (int jj = 0; jj < l; jj++) preds[jj] = arr[jj];
            for (int a = 0; a < l; a++)
                for (int b2_ = a + 1; b2_ < l; b2_++)
                    if (preds[b2_] < preds[a]) { int tm = preds[a]; preds[a] = preds[b2_]; preds[b2_] = tm; }
        }
        sc.lp[k] = (unsigned char)l;
        sc.off[k] = (unsigned short)off;
        sc.invl[k] = (l > 0) ? 1.0f / (float)l : 1.0f;
        for (int jj = 0; jj < 3; jj++) sc.pred[k][jj] = (unsigned char)(jj < l ? preds[jj] : 0);
        int lvl = 0;
        for (int jj = 0; jj < l; jj++) {
            int pl = level[preds[jj]] + 1;
            if (pl > lvl) lvl = pl;
        }
        level[k] = lvl;
        off += l;
    }
    E = off;
    int maxlvl = 0;
    for (int k = 0; k < NC; k++) if (level[k] > maxlvl) maxlvl = level[k];
    sc.nLvl = maxlvl + 1;
    int pos = 0;
    for (int lv = 0; lv <= maxlvl; lv++) {
        sc.lvlStart[lv] = (short)pos;
        for (int k = 0; k < NC; k++)
            if (level[k] == lv) sc.order[pos++] = (unsigned char)k;
    }
    sc.lvlStart[maxlvl + 1] = (short)pos;
}
} // namespace

extern "C" void kernel_launch(void* const* d_in, const int* in_sizes, int n_in,
                              void* d_out, int out_size)
{
    Sched sc; int E;
    build_graph(sc, E);

    const int*   uid    = (const int*)  d_in[0];
    const int*   qid    = (const int*)  d_in[1];
    const float* priori = (const float*)d_in[2];
    const float* cpd    = (const float*)d_in[3];
    const float* cnd    = (const float*)d_in[4];
    const float* idiff  = (const float*)d_in[5];
    const float* idisc  = (const float*)d_in[6];
    const float* qt     = (const float*)d_in[7];
    const float* bu     = (const float*)d_in[9];
    const float* bi     = (const float*)d_in[11];
    const float* b1     = (const float*)d_in[13];
    const float* W2     = (const float*)d_in[14];
    const float* b2     = (const float*)d_in[15];
    float* out = (float*)d_out;

    int Ein = in_sizes[3] / NUM_USER;
    if (Ein > 0 && Ein <= MAXE) E = Ein;

    static bool attr_done = false;
    if (!attr_done) {
        cudaFuncSetAttribute(k_factor, cudaFuncAttributeMaxDynamicSharedMemorySize, SMEM_FACTOR);
        cudaFuncSetAttribute(k_mlp,    cudaFuncAttributeMaxDynamicSharedMemorySize, SMEM_MLP);
        attr_done = true;
    }

    k_front<<<NB_MAST + NB_PACK, 256>>>(uid, qid, priori, cpd, cnd, qt,
                                        idiff, idisc,
                                        (const float*)d_in[8], (const float*)d_in[10],
                                        (const float*)d_in[12], sc, E);

    k_factor<<<dim3(BATCH / 128, DH / 64), 256, SMEM_FACTOR>>>(bu, bi);

    k_mlp<<<dim3(BATCH / 128, H2 / 128), 256, SMEM_MLP>>>(b1, W2, b2, out);
}

// round 16
// speedup vs baseline: 1.3836x; 1.3836x over previous
#include <cuda_runtime.h>
#include <cuda_bf16.h>
#include <cstdint>

#define NUM_USER     200000
#define NUM_QUESTION 20000
#define NC           128
#define DH           512
#define H2           256
#define BATCH        16384
#define MAXE         384
#define KW           (NC / 2)
#define DHW          (DH / 2)

// k_factor: single stage, BK=128 (whole K). 384 rows x 68 u32.
#define LDSF         68
#define SMEM_FACTOR  (384 * LDSF * 4)     // 104448 B
// k_mlp: BK=64, stage = 256 rows x 36 u32, 3 stages
#define LDS2         36
#define M_STAGEU     (256 * LDS2)
#define SMEM_MLP     (3 * M_STAGEU * 4)   // 110592 B

#define NB_MAST      (BATCH / 8)
#define NB_PACK      ((BATCH * KW + 255) / 256)

// ---------------- scratch (__device__ globals) ----------------
__device__ uint32_t g_Bm2[BATCH * KW];
__device__ float    g_Disc[BATCH];
__device__ uint32_t g_A2 [BATCH * KW];
__device__ uint32_t g_X2 [BATCH * DHW];
__device__ float    g_P  [2 * BATCH];
__device__ int      g_cnt[BATCH / 128];
__device__ uint32_t g_Wu2[DH * KW];
__device__ uint32_t g_Wi2[DH * KW];
__device__ uint32_t g_W12[H2 * DHW];

struct Sched {
    unsigned char  order[NC];
    unsigned char  lp[NC];
    unsigned short off[NC];
    unsigned char  pred[NC][3];
    float          invl[NC];
    short          lvlStart[NC + 1];
    int            nLvl;
};

__device__ __forceinline__ float sigmoidf(float x) {          // exact (mastery/final)
    return __fdividef(1.0f, 1.0f + __expf(-x));
}
__device__ __forceinline__ float tanha(float x) {             // 1 MUFU
    float y;
    asm("tanh.approx.f32 %0, %1;" : "=f"(y) : "f"(x));
    return y;
}
__device__ __forceinline__ float sigma(float x) {             // 1 MUFU + FMA (GEMM epilogues)
    return fmaf(tanha(0.5f * x), 0.5f, 0.5f);
}
__device__ __forceinline__ uint32_t packbf(float x, float y) {
    __nv_bfloat162 v = __floats2bfloat162_rn(x, y);
    return *(uint32_t*)&v;
}
__device__ __forceinline__ uint32_t smem_u32(const void* p) {
    uint32_t a;
    asm("{ .reg .u64 t; cvta.to.shared.u64 t, %1; cvt.u32.u64 %0, t; }" : "=r"(a) : "l"(p));
    return a;
}
__device__ __forceinline__ void cp16(uint32_t s, const void* g) {
    asm volatile("cp.async.cg.shared.global [%0], [%1], 16;" :: "r"(s), "l"(g));
}
__device__ __forceinline__ void cp_commit() {
    asm volatile("cp.async.commit_group;" ::: "memory");
}
__device__ __forceinline__ void cp_wait0() {
    asm volatile("cp.async.wait_group 0;" ::: "memory");
}
__device__ __forceinline__ void cp_wait1() {
    asm volatile("cp.async.wait_group 1;" ::: "memory");
}
__device__ __forceinline__ void ldsm4(uint32_t r[4], uint32_t addr) {
    asm volatile("ldmatrix.sync.aligned.m8n8.x4.shared.b16 {%0,%1,%2,%3}, [%4];"
        : "=r"(r[0]), "=r"(r[1]), "=r"(r[2]), "=r"(r[3]) : "r"(addr));
}
__device__ __forceinline__ void mma_bf16(float c[4],
                                         uint32_t a0, uint32_t a1, uint32_t a2, uint32_t a3,
                                         uint32_t b0, uint32_t b1) {
    asm volatile(
        "mma.sync.aligned.m16n8k16.row.col.f32.bf16.bf16.f32 "
        "{%0,%1,%2,%3}, {%4,%5,%6,%7}, {%8,%9}, {%0,%1,%2,%3};"
        : "+f"(c[0]), "+f"(c[1]), "+f"(c[2]), "+f"(c[3])
        : "r"(a0), "r"(a1), "r"(a2), "r"(a3), "r"(b0), "r"(b1));
}

// ---------------- K0: merged front end -------------------------------------
#define WPB 8
#define NIT (MAXE / 32)
__global__ void __launch_bounds__(256) k_front(
    const int* __restrict__ uid, const int* __restrict__ qid,
    const float* __restrict__ priori,
    const float* __restrict__ condi_p, const float* __restrict__ condi_n,
    const float* __restrict__ qt,
    const float* __restrict__ idiff, const float* __restrict__ idisc,
    const float* __restrict__ Wu, const float* __restrict__ Wi,
    const float* __restrict__ W1,
    Sched s, int E)
{
    if (blockIdx.x >= NB_MAST) {
        // ---- pack part ----
        int idx = (blockIdx.x - NB_MAST) * blockDim.x + threadIdx.x;
        if (idx >= BATCH * KW) return;
        if (idx < DH * KW) {
            g_Wu2[idx] = packbf(Wu[2 * idx], Wu[2 * idx + 1]);
            g_Wi2[idx] = packbf(Wi[2 * idx], Wi[2 * idx + 1]);
        }
        if (idx < H2 * DHW)
            g_W12[idx] = packbf(W1[2 * idx], W1[2 * idx + 1]);
        int b = idx >> 6, j = idx & 63;
        int q = qid[b];
        size_t base = (size_t)q * NC + 2 * j;
        float v0 = sigma(idiff[base])     * qt[base];
        float v1 = sigma(idiff[base + 1]) * qt[base + 1];
        g_Bm2[idx] = packbf(v0, v1);
        if (j == 0) g_Disc[b] = sigma(idisc[q]);
        return;
    }

    // ---- mastery part ----
    __shared__ float sm_m [WPB][NC];
    __shared__ float sm_cp[WPB][MAXE];
    __shared__ float sm_cn[WPB][MAXE];
    // Sched staged to shared: kills divergent constant-memory replays
    __shared__ unsigned char  sh_order[NC], sh_lp[NC];
    __shared__ unsigned short sh_off[NC];
    __shared__ unsigned char  sh_pred[NC][3];
    __shared__ float          sh_invl[NC];
    __shared__ short          sh_lvl[NC + 1];

    int t = threadIdx.x;
    if (t < NC) {
        sh_order[t]  = s.order[t];
        sh_lp[t]     = s.lp[t];
        sh_off[t]    = s.off[t];
        sh_invl[t]   = s.invl[t];
        sh_pred[t][0] = s.pred[t][0];
        sh_pred[t][1] = s.pred[t][1];
        sh_pred[t][2] = s.pred[t][2];
        sh_lvl[t]    = s.lvlStart[t];
    }
    if (t == NC) sh_lvl[NC] = s.lvlStart[NC];
    __syncthreads();

    int lane = t & 31, w = t >> 5;
    int b = blockIdx.x * WPB + w;
    int u = uid[b];

    const float* cpr = condi_p + (size_t)u * E;
    const float* cnr = condi_n + (size_t)u * E;

    float rcp[NIT], rcn[NIT];
    #pragma unroll
    for (int it = 0; it < NIT; it++) {
        int j = lane + it * 32;
        if (j < E) { rcp[it] = __ldg(cpr + j); rcn[it] = __ldg(cnr + j); }
    }
    #pragma unroll
    for (int it = 0; it < NIT; it++) {
        int j = lane + it * 32;
        if (j < E) {
            sm_cp[w][j] = sigmoidf(rcp[it]);
            sm_cn[w][j] = sigmoidf(rcn[it]);
        }
    }
    __syncwarp();

    const float* pr = priori + (size_t)u * NC;
    int nLvl = s.nLvl;
    for (int lv = 0; lv < nLvl; lv++) {
        int e = sh_lvl[lv + 1];
        for (int i = sh_lvl[lv] + lane; i < e; i += 32) {
            int k = sh_order[i];
            int l = sh_lp[k];
            float v;
            if (l == 0) {
                v = sigmoidf(pr[k]);
            } else {
                int o = sh_off[k];
                float inv = sh_invl[k];
                v = 1.0f;
                #pragma unroll 1
                for (int j = 0; j < l; j++) {
                    float mp = sm_m[w][sh_pred[k][j]];
                    float a = sm_cp[w][o + j], bb = sm_cn[w][o + j];
                    if (l > 1) { a = __powf(a, inv); bb = __powf(bb, inv); }
                    v *= a * mp + bb * (1.0f - mp);
                }
            }
            sm_m[w][k] = v;
        }
        __syncwarp();
    }

    int q = qid[b];
    const float* qr = qt + (size_t)q * NC;
    uint32_t* ao = g_A2 + (size_t)b * KW;
    for (int j = lane; j < KW; j += 32)
        ao[j] = packbf(sm_m[w][2 * j] * qr[2 * j], sm_m[w][2 * j + 1] * qr[2 * j + 1]);
}

// ---------------- K2: fused dual bf16 GEMM -> X  (128M x 64N, BK=128, 1 stage) -----
__global__ void __launch_bounds__(256, 2) k_factor(const float* __restrict__ bu,
                                                   const float* __restrict__ bi)
{
    extern __shared__ uint32_t smx[];
    int t = threadIdx.x, lane = t & 31, warp = t >> 5;
    int wm = (warp & 1) * 64;
    int wn = (warp >> 1) * 16;
    int m0 = blockIdx.x * 128, n0 = blockIdx.y * 64;
    int g   = lane >> 2;
    int tig = lane & 3;
    int lr  = lane & 15;
    int lk  = (lane >> 4) * 4;

    const uint32_t* Ab  = g_A2  + (size_t)m0 * KW;
    const uint32_t* Bmb = g_Bm2 + (size_t)m0 * KW;
    const uint32_t* Wub = g_Wu2 + (size_t)n0 * KW;
    const uint32_t* Wib = g_Wi2 + (size_t)n0 * KW;

    int cr = t >> 4;
    int cc = (t & 15) * 4;

    uint32_t sb = smem_u32(smx);
    #pragma unroll
    for (int i = 0; i < 24; i++) {
        int smrow = i * 16 + cr;
        const uint32_t* src;
        if      (i < 8)  src = Ab  + (size_t)(i * 16 + cr) * KW;
        else if (i < 16) src = Bmb + (size_t)((i - 8) * 16 + cr) * KW;
        else if (i < 20) src = Wub + (size_t)((i - 16) * 16 + cr) * KW;
        else             src = Wib + (size_t)((i - 20) * 16 + cr) * KW;
        cp16(sb + (uint32_t)(smrow * LDSF + cc) * 4, src + cc);
    }
    cp_commit();
    cp_wait0();
    __syncthreads();

    float cU[4][2][4], cI[4][2][4];
    #pragma unroll
    for (int mi = 0; mi < 4; mi++)
        #pragma unroll
        for (int ni = 0; ni < 2; ni++)
            #pragma unroll
            for (int q = 0; q < 4; q++) { cU[mi][ni][q] = 0.f; cI[mi][ni][q] = 0.f; }

    #pragma unroll
    for (int kk = 0; kk < 8; kk++) {
        int kb = kk * 8;
        uint32_t fu[4], fi[4], aA[4][4], aB[4][4];
        ldsm4(fu, sb + 4u * ((256 + wn + lr) * LDSF + kb + lk));
        ldsm4(fi, sb + 4u * ((320 + wn + lr) * LDSF + kb + lk));
        #pragma unroll
        for (int mi = 0; mi < 4; mi++) {
            int rb = wm + mi * 16 + lr;
            ldsm4(aA[mi], sb + 4u * (rb * LDSF + kb + lk));
            ldsm4(aB[mi], sb + 4u * ((128 + rb) * LDSF + kb + lk));
        }
        #pragma unroll
        for (int mi = 0; mi < 4; mi++) {
            mma_bf16(cU[mi][0], aA[mi][0], aA[mi][1], aA[mi][2], aA[mi][3], fu[0], fu[2]);
            mma_bf16(cU[mi][1], aA[mi][0], aA[mi][1], aA[mi][2], aA[mi][3], fu[1], fu[3]);
            mma_bf16(cI[mi][0], aB[mi][0], aB[mi][1], aB[mi][2], aB[mi][3], fi[0], fi[2]);
            mma_bf16(cI[mi][1], aB[mi][0], aB[mi][1], aB[mi][2], aB[mi][3], fi[1], fi[3]);
        }
    }

    #pragma unroll
    for (int mi = 0; mi < 4; mi++) {
        int r0 = m0 + wm + mi * 16 + g;
        float d0 = g_Disc[r0], d1 = g_Disc[r0 + 8];
        #pragma unroll
        for (int ni = 0; ni < 2; ni++) {
            int col = n0 + wn + ni * 8 + tig * 2;
            float bu0 = bu[col], bu1 = bu[col + 1];
            float bi0 = bi[col], bi1 = bi[col + 1];
            float x00 = (tanha(cU[mi][ni][0] + bu0) - sigma(cI[mi][ni][0] + bi0)) * d0;
            float x01 = (tanha(cU[mi][ni][1] + bu1) - sigma(cI[mi][ni][1] + bi1)) * d0;
            float x10 = (tanha(cU[mi][ni][2] + bu0) - sigma(cI[mi][ni][2] + bi0)) * d1;
            float x11 = (tanha(cU[mi][ni][3] + bu1) - sigma(cI[mi][ni][3] + bi1)) * d1;
            g_X2[(size_t)r0 * DHW + (col >> 1)]       = packbf(x00, x01);
            g_X2[(size_t)(r0 + 8) * DHW + (col >> 1)] = packbf(x10, x11);
        }
    }
}

// ---------------- K3: bf16 GEMM + fused GEMV + final combine ----------------
__global__ void __launch_bounds__(256, 2) k_mlp(const float* __restrict__ bias,
                                                const float* __restrict__ W2,
                                                const float* __restrict__ b2,
                                                float* __restrict__ out)
{
    extern __shared__ uint32_t smx[];
    int t = threadIdx.x, lane = t & 31, warp = t >> 5;
    int wm = (warp & 1) * 64;
    int wn = (warp >> 1) * 32;
    int m0 = blockIdx.x * 128, n0 = blockIdx.y * 128;
    int g   = lane >> 2;
    int tig = lane & 3;
    int lr  = lane & 15;
    int lk  = (lane >> 4) * 4;

    const uint32_t* Ab = g_X2  + (size_t)m0 * DHW;
    const uint32_t* Wb = g_W12 + (size_t)n0 * DHW;

    int cr = t >> 3;
    int cc = (t & 7) * 4;

    float acc[4][4][4];
    #pragma unroll
    for (int mi = 0; mi < 4; mi++)
        #pragma unroll
        for (int ni = 0; ni < 4; ni++)
            #pragma unroll
            for (int q = 0; q < 4; q++) acc[mi][ni][q] = 0.f;

    const int NCH = 8;

    auto issue = [&](int ch, uint32_t* st) {
        uint32_t sb = smem_u32(st);
        int kc = ch * 32;
        #pragma unroll
        for (int i = 0; i < 8; i++) {
            int smrow = i * 32 + cr;
            const uint32_t* src = (i < 4) ? Ab + (size_t)(i * 32 + cr) * DHW
                                          : Wb + (size_t)((i - 4) * 32 + cr) * DHW;
            cp16(sb + (uint32_t)(smrow * LDS2 + cc) * 4, src + kc + cc);
        }
    };

    issue(0, smx);             cp_commit();
    issue(1, smx + M_STAGEU);  cp_commit();

    #pragma unroll
    for (int ch = 0; ch < NCH; ch++) {
        cp_wait1();
        __syncthreads();
        if (ch + 2 < NCH) {
            int s2 = (ch + 2) % 3;
            issue(ch + 2, smx + s2 * M_STAGEU);
        }
        cp_commit();
        uint32_t sb = smem_u32(smx + (ch % 3) * M_STAGEU);
        #pragma unroll
        for (int kk = 0; kk < 4; kk++) {
            int kb = kk * 8;
            uint32_t f0[4], f1[4], a[4][4];
            ldsm4(f0, sb + 4u * ((128 + wn + lr) * LDS2 + kb + lk));
            ldsm4(f1, sb + 4u * ((144 + wn + lr) * LDS2 + kb + lk));
            #pragma unroll
            for (int mi = 0; mi < 4; mi++)
                ldsm4(a[mi], sb + 4u * ((wm + mi * 16 + lr) * LDS2 + kb + lk));
            #pragma unroll
            for (int mi = 0; mi < 4; mi++) {
                mma_bf16(acc[mi][0], a[mi][0], a[mi][1], a[mi][2], a[mi][3], f0[0], f0[2]);
                mma_bf16(acc[mi][1], a[mi][0], a[mi][1], a[mi][2], a[mi][3], f0[1], f0[3]);
                mma_bf16(acc[mi][2], a[mi][0], a[mi][1], a[mi][2], a[mi][3], f1[0], f1[2]);
                mma_bf16(acc[mi][3], a[mi][0], a[mi][1], a[mi][2], a[mi][3], f1[1], f1[3]);
            }
        }
        __syncthreads();
    }

    float w2v[8], bv[8];
    #pragma unroll
    for (int ni = 0; ni < 4; ni++) {
        int col = n0 + wn + ni * 8 + tig * 2;
        w2v[ni * 2]     = W2[col];
        w2v[ni * 2 + 1] = W2[col + 1];
        bv [ni * 2]     = bias[col];
        bv [ni * 2 + 1] = bias[col + 1];
    }
    float part[8];
    #pragma unroll
    for (int j = 0; j < 8; j++) part[j] = 0.f;
    #pragma unroll
    for (int mi = 0; mi < 4; mi++)
        #pragma unroll
        for (int ni = 0; ni < 4; ni++) {
            float b0 = bv[ni * 2], b1v = bv[ni * 2 + 1];
            float w0 = w2v[ni * 2], w1 = w2v[ni * 2 + 1];
            part[mi * 2]     += sigma(acc[mi][ni][0] + b0) * w0
                              + sigma(acc[mi][ni][1] + b1v) * w1;
            part[mi * 2 + 1] += sigma(acc[mi][ni][2] + b0) * w0
                              + sigma(acc[mi][ni][3] + b1v) * w1;
        }
    #pragma unroll
    for (int j = 0; j < 8; j++) {
        part[j] += __shfl_xor_sync(0xffffffffu, part[j], 1);
        part[j] += __shfl_xor_sync(0xffffffffu, part[j], 2);
    }
    float* sP = (float*)smx;
    if (tig == 0) {
        #pragma unroll
        for (int mi = 0; mi < 4; mi++) {
            int rl = wm + mi * 16 + g;
            sP[(warp >> 1) * 128 + rl]     = part[mi * 2];
            sP[(warp >> 1) * 128 + rl + 8] = part[mi * 2 + 1];
        }
    }
    __syncthreads();
    if (t < 128) {
        float s = sP[t] + sP[128 + t] + sP[256 + t] + sP[384 + t];
        g_P[(size_t)blockIdx.y * BATCH + m0 + t] = s;
    }

    __threadfence();
    __syncthreads();
    __shared__ int s_old;
    if (t == 0) s_old = atomicAdd(&g_cnt[blockIdx.x], 1);
    __syncthreads();
    if (s_old == 1) {
        __threadfence();
        if (t < 128) {
            float s = g_P[m0 + t] + g_P[BATCH + m0 + t] + b2[0];
            out[m0 + t] = sigmoidf(s);
        }
        if (t == 0) g_cnt[blockIdx.x] = 0;
    }
}

// ---------------- host: numpy-legacy MT19937 graph reconstruction ----------------
namespace {
struct MT { uint32_t mt[624]; int idx; };
static void mt_seed(MT& s, uint32_t seed) {
    s.mt[0] = seed;
    for (int i = 1; i < 624; i++)
        s.mt[i] = 1812433253u * (s.mt[i-1] ^ (s.mt[i-1] >> 30)) + (uint32_t)i;
    s.idx = 624;
}
static uint32_t mt_next(MT& s) {
    if (s.idx >= 624) {
        for (int i = 0; i < 624; i++) {
            uint32_t y = (s.mt[i] & 0x80000000u) | (s.mt[(i+1) % 624] & 0x7fffffffu);
            s.mt[i] = s.mt[(i+397) % 624] ^ (y >> 1) ^ ((y & 1u) ? 0x9908b0dfu : 0u);
        }
        s.idx = 0;
    }
    uint32_t y = s.mt[s.idx++];
    y ^= y >> 11;
    y ^= (y << 7)  & 0x9d2c5680u;
    y ^= (y << 15) & 0xefc60000u;
    y ^= y >> 18;
    return y;
}
static uint32_t draw_bounded(MT& s, uint32_t rng) {
    uint32_t mask = rng; mask |= mask >> 1; mask |= mask >> 2; mask |= mask >> 4;
    mask |= mask >> 8; mask |= mask >> 16;
    uint32_t v;
    do { v = mt_next(s) & mask; } while (v > rng);
    return v;
}
static void build_graph(Sched& sc, int& E) {
    MT mt; mt_seed(mt, 0u);
    int off = 0;
    int level[NC];
    for (int k = 0; k < NC; k++) {
        int l = 0;
        if (k > 0) {
            int hi = (k < 3 ? k : 3) + 1;
            l = (int)draw_bounded(mt, (uint32_t)(hi - 1));
        }
        int preds[3] = {0, 0, 0};
        if (l > 0) {
            int arr[NC];
            for (int i = 0; i < k; i++) arr[i] = i;
            for (int i = k - 1; i >= 1; i--) {
                uint32_t j = draw_bounded(mt, (uint32_t)i);
                int tmp = arr[i]; arr[i] = arr[(int)j]; arr[(int)j] = tmp;
            }
            for (int jj = 0; jj < l; jj++) preds[jj] = arr[jj];
            for (int a = 0; a < l; a++)
                for (int b2_ = a + 1; b2_ < l; b2_++)
                    if (preds[b2_] < preds[a]) { int tm = preds[a]; preds[a] = preds[b2_]; preds[b2_] = tm; }
        }
        sc.lp[k] = (unsigned char)l;
        sc.off[k] = (unsigned short)off;
        sc.invl[k] = (l > 0) ? 1.0f / (float)l : 1.0f;
        for (int jj = 0; jj < 3; jj++) sc.pred[k][jj] = (unsigned char)(jj < l ? preds[jj] : 0);
        int lvl = 0;
        for (int jj = 0; jj < l; jj++) {
            int pl = level[preds[jj]] + 1;
            if (pl > lvl) lvl = pl;
        }
        level[k] = lvl;
        off += l;
    }
    E = off;
    int maxlvl = 0;
    for (int k = 0; k < NC; k++) if (level[k] > maxlvl) maxlvl = level[k];
    sc.nLvl = maxlvl + 1;
    int pos = 0;
    for (int lv = 0; lv <= maxlvl; lv++) {
        sc.lvlStart[lv] = (short)pos;
        for (int k = 0; k < NC; k++)
            if (level[k] == lv) sc.order[pos++] = (unsigned char)k;
    }
    sc.lvlStart[maxlvl + 1] = (short)pos;
}
} // namespace

extern "C" void kernel_launch(void* const* d_in, const int* in_sizes, int n_in,
                              void* d_out, int out_size)
{
    Sched sc; int E;
    build_graph(sc, E);

    const int*   uid    = (const int*)  d_in[0];
    const int*   qid    = (const int*)  d_in[1];
    const float* priori = (const float*)d_in[2];
    const float* cpd    = (const float*)d_in[3];
    const float* cnd    = (const float*)d_in[4];
    const float* idiff  = (const float*)d_in[5];
    const float* idisc  = (const float*)d_in[6];
    const float* qt     = (const float*)d_in[7];
    const float* bu     = (const float*)d_in[9];
    const float* bi     = (const float*)d_in[11];
    const float* b1     = (const float*)d_in[13];
    const float* W2     = (const float*)d_in[14];
    const float* b2     = (const float*)d_in[15];
    float* out = (float*)d_out;

    int Ein = in_sizes[3] / NUM_USER;
    if (Ein > 0 && Ein <= MAXE) E = Ein;

    static bool attr_done = false;
    if (!attr_done) {
        cudaFuncSetAttribute(k_factor, cudaFuncAttributeMaxDynamicSharedMemorySize, SMEM_FACTOR);
        cudaFuncSetAttribute(k_mlp,    cudaFuncAttributeMaxDynamicSharedMemorySize, SMEM_MLP);
        attr_done = true;
    }

    k_front<<<NB_MAST + NB_PACK, 256>>>(uid, qid, priori, cpd, cnd, qt,
                                        idiff, idisc,
                                        (const float*)d_in[8], (const float*)d_in[10],
                                        (const float*)d_in[12], sc, E);

    k_factor<<<dim3(BATCH / 128, DH / 64), 256, SMEM_FACTOR>>>(bu, bi);

    k_mlp<<<dim3(BATCH / 128, H2 / 128), 256, SMEM_MLP>>>(b1, W2, b2, out);
}